// round 1
// baseline (speedup 1.0000x reference)
#include <cuda_runtime.h>
#include <math.h>

// Problem constants (fixed by setup_inputs)
#define DIM   256
#define NHEAD 8
#define DHEAD 32
#define NLVL  4
#define LQ    16320
#define PROJN 768   // [cso 256 | tso 256 | caw 128 | taw 128]

// Scratch (device globals: allowed, no runtime alloc)
__device__ float g_value[LQ * DIM];
__device__ float g_proj [LQ * PROJN];
__device__ float g_mid  [LQ * DIM];

// ---------------- SGEMM with bias: C = A(MxK) * B(KxN) + bias ----------------
// Row-major. M=16320 (mult of 64), N mult of 64, K=256 (mult of 16).
#define BM 64
#define BN 64
#define BK 16

__global__ __launch_bounds__(256) void sgemm_bias(
    const float* __restrict__ A, const float* __restrict__ B,
    const float* __restrict__ bias, float* __restrict__ C,
    int K, int ldb, int ldc)
{
    __shared__ float As[BK][BM];
    __shared__ float Bs[BK][BN];

    const int bm = blockIdx.y * BM;
    const int bn = blockIdx.x * BN;
    const int tid = threadIdx.x;
    const int tx = tid & 15;        // 0..15 -> 4 cols each
    const int ty = tid >> 4;        // 0..15 -> 4 rows each

    float acc[4][4] = {};

    for (int k0 = 0; k0 < K; k0 += BK) {
        // Load A tile (64x16): each thread loads float4 along K
        {
            int m  = tid >> 2;            // 0..63
            int kq = (tid & 3) << 2;      // 0,4,8,12
            float4 av = *(const float4*)(A + (size_t)(bm + m) * K + k0 + kq);
            As[kq + 0][m] = av.x;
            As[kq + 1][m] = av.y;
            As[kq + 2][m] = av.z;
            As[kq + 3][m] = av.w;
        }
        // Load B tile (16x64): each thread loads float4 along N
        {
            int kk = tid >> 4;            // 0..15
            int nq = (tid & 15) << 2;     // 0..60
            float4 bv = *(const float4*)(B + (size_t)(k0 + kk) * ldb + bn + nq);
            *(float4*)(&Bs[kk][nq]) = bv;
        }
        __syncthreads();

        #pragma unroll
        for (int kk = 0; kk < BK; ++kk) {
            float a[4], b[4];
            #pragma unroll
            for (int i = 0; i < 4; ++i) a[i] = As[kk][(ty << 2) + i];
            #pragma unroll
            for (int j = 0; j < 4; ++j) b[j] = Bs[kk][(tx << 2) + j];
            #pragma unroll
            for (int i = 0; i < 4; ++i)
                #pragma unroll
                for (int j = 0; j < 4; ++j)
                    acc[i][j] += a[i] * b[j];
        }
        __syncthreads();
    }

    #pragma unroll
    for (int i = 0; i < 4; ++i) {
        int mrow = bm + (ty << 2) + i;
        int ncol = bn + (tx << 2);
        float4 o;
        o.x = acc[i][0] + bias[ncol + 0];
        o.y = acc[i][1] + bias[ncol + 1];
        o.z = acc[i][2] + bias[ncol + 2];
        o.w = acc[i][3] + bias[ncol + 3];
        *(float4*)(C + (size_t)mrow * ldc + ncol) = o;
    }
}

// ---------------- Deformable sampling + softmax ----------------
// Block = one query (256 threads = 8 warps). Warp w = head w. Lane = point
// during setup, lane = channel during accumulation.
__global__ __launch_bounds__(256) void deform_kernel(
    const float* __restrict__ proj,    // LQ x 768
    const float* __restrict__ value,   // LQ x 256 (pix-major, h*32+c inner)
    const float* __restrict__ refp,    // LQ x 4 x 2
    const float* __restrict__ toff,    // LQ x 4 x 2 x 2
    float* __restrict__ mid)           // LQ x 256
{
    __shared__ float4 smw[256];
    __shared__ int4   sma[256];

    const int q    = blockIdx.x;
    const int warp = threadIdx.x >> 5;   // head
    const int lane = threadIdx.x & 31;
    const int h = warp;
    const int l = lane >> 3;             // level
    const int p = lane & 7;              // point within level

    // Level constants: W, T*H, level start pixel
    const int   Wl[4]  = {64, 32, 16, 8};
    const int   THl[4] = {192, 96, 48, 24};
    const int   STl[4] = {0, 12288, 15360, 16128};
    const int   Wv = Wl[l], TH = THl[l], start = STl[l];
    const float invW = 1.0f / (float)Wv, invTH = 1.0f / (float)TH;

    const float* prow = proj + (size_t)q * PROJN;

    // ---- logit for this lane's (l,p), joint softmax over 32 ----
    int logit_col = (p < 4) ? (512 + h * 16 + l * 4 + p)
                            : (640 + h * 16 + l * 4 + (p - 4));
    float logit = prow[logit_col];
    float mx = logit;
    #pragma unroll
    for (int off = 16; off; off >>= 1) mx = fmaxf(mx, __shfl_xor_sync(0xffffffffu, mx, off));
    float e = __expf(logit - mx);
    float s = e;
    #pragma unroll
    for (int off = 16; off; off >>= 1) s += __shfl_xor_sync(0xffffffffu, s, off);
    float attnw = e / s;

    // ---- sampling location ----
    float rx = refp[q * 8 + l * 2 + 0];
    float ry = refp[q * 8 + l * 2 + 1];
    float ox, oy;
    if (p < 4) {
        int col = ((h * 4 + l) * 4 + p) * 2;                 // cso
        ox = prow[col + 0] * invW;
        oy = prow[col + 1] * invTH;
    } else {
        int tw = (p - 4) >> 1, tp = (p - 4) & 1;
        int col = 256 + (((h * 4 + l) * 2 + tw) * 2 + tp) * 2;  // tso
        int tob = ((q * 4 + l) * 2 + tw) * 2;
        ox = toff[tob + 0] + prow[col + 0] * invW;
        oy = toff[tob + 1] + prow[col + 1] * invTH;
    }
    float x = (rx + ox) * (float)Wv - 0.5f;
    float y = (ry + oy) * (float)TH - 0.5f;

    float x0f = floorf(x), y0f = floorf(y);
    float lx = x - x0f, ly = y - y0f;
    int x0 = (int)x0f, y0 = (int)y0f;
    int x1 = x0 + 1,   y1 = y0 + 1;

    bool ix0 = (x0 >= 0) & (x0 < Wv);
    bool ix1 = (x1 >= 0) & (x1 < Wv);
    bool iy0 = (y0 >= 0) & (y0 < TH);
    bool iy1 = (y1 >= 0) & (y1 < TH);
    int cx0 = min(max(x0, 0), Wv - 1);
    int cx1 = min(max(x1, 0), Wv - 1);
    int cy0 = min(max(y0, 0), TH - 1);
    int cy1 = min(max(y1, 0), TH - 1);

    float4 w;
    w.x = attnw * (1.f - lx) * (1.f - ly) * (float)(ix0 & iy0);
    w.y = attnw * lx         * (1.f - ly) * (float)(ix1 & iy0);
    w.z = attnw * (1.f - lx) * ly         * (float)(ix0 & iy1);
    w.w = attnw * lx         * ly         * (float)(ix1 & iy1);

    const int hbase = h * DHEAD;
    int4 a;
    a.x = (start + cy0 * Wv + cx0) * DIM + hbase;
    a.y = (start + cy0 * Wv + cx1) * DIM + hbase;
    a.z = (start + cy1 * Wv + cx0) * DIM + hbase;
    a.w = (start + cy1 * Wv + cx1) * DIM + hbase;

    smw[threadIdx.x] = w;
    sma[threadIdx.x] = a;
    __syncwarp();

    // ---- accumulate: lane = channel, loop over the warp's 32 points ----
    float acc = 0.f;
    const int sbase = warp << 5;
    #pragma unroll 4
    for (int i = 0; i < 32; ++i) {
        float4 wi = smw[sbase + i];
        int4   ai = sma[sbase + i];
        acc += wi.x * __ldg(value + ai.x + lane);
        acc += wi.y * __ldg(value + ai.y + lane);
        acc += wi.z * __ldg(value + ai.z + lane);
        acc += wi.w * __ldg(value + ai.w + lane);
    }
    mid[(size_t)q * DIM + hbase + lane] = acc;
}

// ---------------- launch ----------------
extern "C" void kernel_launch(void* const* d_in, const int* in_sizes, int n_in,
                              void* d_out, int out_size)
{
    const float* query = (const float*)d_in[0];
    const float* refp  = (const float*)d_in[1];
    const float* toff  = (const float*)d_in[2];
    const float* inpf  = (const float*)d_in[3];
    // d_in[4], d_in[5]: spatial shapes / level starts (int64) — fixed, hardcoded
    const float* W_so  = (const float*)d_in[6];
    const float* b_so  = (const float*)d_in[7];
    const float* W_tso = (const float*)d_in[8];
    const float* b_tso = (const float*)d_in[9];
    const float* W_aw  = (const float*)d_in[10];
    const float* b_aw  = (const float*)d_in[11];
    const float* W_taw = (const float*)d_in[12];
    const float* b_taw = (const float*)d_in[13];
    const float* W_v   = (const float*)d_in[14];
    const float* b_v   = (const float*)d_in[15];
    const float* W_o   = (const float*)d_in[16];
    const float* b_o   = (const float*)d_in[17];
    float* out = (float*)d_out;

    float *value, *proj, *mid;
    cudaGetSymbolAddress((void**)&value, g_value);
    cudaGetSymbolAddress((void**)&proj,  g_proj);
    cudaGetSymbolAddress((void**)&mid,   g_mid);

    dim3 blk(256);
    // value = input_flatten @ W_v + b_v
    sgemm_bias<<<dim3(DIM / BN, LQ / BM), blk>>>(inpf, W_v, b_v, value, DIM, DIM, DIM);
    // fused projection buffer: [cso | tso | caw | taw]
    sgemm_bias<<<dim3(256 / BN, LQ / BM), blk>>>(query, W_so,  b_so,  proj + 0,   DIM, 256, PROJN);
    sgemm_bias<<<dim3(256 / BN, LQ / BM), blk>>>(query, W_tso, b_tso, proj + 256, DIM, 256, PROJN);
    sgemm_bias<<<dim3(128 / BN, LQ / BM), blk>>>(query, W_aw,  b_aw,  proj + 512, DIM, 128, PROJN);
    sgemm_bias<<<dim3(128 / BN, LQ / BM), blk>>>(query, W_taw, b_taw, proj + 640, DIM, 128, PROJN);
    // softmax + deformable bilinear sampling
    deform_kernel<<<LQ, 256>>>(proj, value, refp, toff, mid);
    // out = mid @ W_o + b_o
    sgemm_bias<<<dim3(DIM / BN, LQ / BM), blk>>>(mid, W_o, b_o, out, DIM, DIM, DIM);
}

// round 2
// speedup vs baseline: 1.1166x; 1.1166x over previous
#include <cuda_runtime.h>
#include <math.h>

// Problem constants (fixed by setup_inputs)
#define DIM   256
#define NHEAD 8
#define DHEAD 32
#define NLVL  4
#define LQ    16320
#define PROJN 768   // [cso 256 | tso 256 | caw 128 | taw 128]

// Scratch (device globals: allowed, no runtime alloc)
__device__ float g_value[LQ * DIM];
__device__ float g_proj [LQ * PROJN];
__device__ float g_mid  [LQ * DIM];

// ---------------- SGEMM v2: 8x8 per-thread register tile ----------------
// C = A(M x 256) * B(256 x N) + bias.  BM=64, BN=128, BK=16, 128 threads.
// A stored transposed in smem (As[k][m], row stride 68 to kill STS conflicts).
#define BM 64
#define BN 128
#define BK 16
#define ASTR 68   // BM + 4 pad (multiple of 4 for LDS.128 alignment)

__global__ __launch_bounds__(128) void sgemm_bias_v2(
    const float* __restrict__ A, const float* __restrict__ B,
    const float* __restrict__ bias, float* __restrict__ C,
    int ldb, int ldc)
{
    __shared__ float As[BK * ASTR];
    __shared__ float Bs[BK * BN];

    const int tid = threadIdx.x;
    const int bm = blockIdx.y * BM;
    const int bn = blockIdx.x * BN;
    const int tx = tid & 15;   // 16 threads in N
    const int ty = tid >> 4;   // 8 threads in M

    // global-load mappings (fully coalesced 128B per lane-quad/octet)
    const int ar = tid >> 2;          // 0..31 (A row within tile)
    const int ac = (tid & 3) << 2;    // 0,4,8,12 (A col quad)
    const int br = tid >> 3;          // 0..15 (B row)
    const int bc = (tid & 7) << 2;    // 0..28 (B col quad base)

    float acc[8][8] = {};

    const float* Abase = A + (size_t)(bm + ar) * 256 + ac;

    for (int k0 = 0; k0 < 256; k0 += BK) {
        // Load A 64x16 -> transposed smem
        #pragma unroll
        for (int it = 0; it < 2; ++it) {
            float4 v = *(const float4*)(Abase + (size_t)it * 32 * 256 + k0);
            int m = ar + it * 32;
            As[(ac + 0) * ASTR + m] = v.x;
            As[(ac + 1) * ASTR + m] = v.y;
            As[(ac + 2) * ASTR + m] = v.z;
            As[(ac + 3) * ASTR + m] = v.w;
        }
        // Load B 16x128
        #pragma unroll
        for (int it = 0; it < 4; ++it) {
            float4 v = *(const float4*)(B + (size_t)(k0 + br) * ldb + bn + bc + it * 32);
            *(float4*)&Bs[br * BN + bc + it * 32] = v;
        }
        __syncthreads();

        #pragma unroll
        for (int kk = 0; kk < BK; ++kk) {
            float4 a0 = *(const float4*)&As[kk * ASTR + (ty << 2)];
            float4 a1 = *(const float4*)&As[kk * ASTR + 32 + (ty << 2)];
            float4 b0 = *(const float4*)&Bs[kk * BN + (tx << 2)];
            float4 b1 = *(const float4*)&Bs[kk * BN + 64 + (tx << 2)];
            float a[8] = {a0.x, a0.y, a0.z, a0.w, a1.x, a1.y, a1.z, a1.w};
            float b[8] = {b0.x, b0.y, b0.z, b0.w, b1.x, b1.y, b1.z, b1.w};
            #pragma unroll
            for (int i = 0; i < 8; ++i)
                #pragma unroll
                for (int j = 0; j < 8; ++j)
                    acc[i][j] += a[i] * b[j];
        }
        __syncthreads();
    }

    // Epilogue: rows {ty*4+i, 32+ty*4+i}, cols {tx*4+j, 64+tx*4+j}
    float4 bs0 = *(const float4*)(bias + bn + (tx << 2));
    float4 bs1 = *(const float4*)(bias + bn + 64 + (tx << 2));
    #pragma unroll
    for (int half = 0; half < 2; ++half) {
        #pragma unroll
        for (int i = 0; i < 4; ++i) {
            int ai = half * 4 + i;
            int mrow = bm + half * 32 + (ty << 2) + i;
            float4 o0, o1;
            o0.x = acc[ai][0] + bs0.x; o0.y = acc[ai][1] + bs0.y;
            o0.z = acc[ai][2] + bs0.z; o0.w = acc[ai][3] + bs0.w;
            o1.x = acc[ai][4] + bs1.x; o1.y = acc[ai][5] + bs1.y;
            o1.z = acc[ai][6] + bs1.z; o1.w = acc[ai][7] + bs1.w;
            *(float4*)(C + (size_t)mrow * ldc + bn + (tx << 2)) = o0;
            *(float4*)(C + (size_t)mrow * ldc + bn + 64 + (tx << 2)) = o1;
        }
    }
}

// ---------------- Deformable sampling + softmax ----------------
__global__ __launch_bounds__(256) void deform_kernel(
    const float* __restrict__ proj,    // LQ x 768
    const float* __restrict__ value,   // LQ x 256 (pix-major, h*32+c inner)
    const float* __restrict__ refp,    // LQ x 4 x 2
    const float* __restrict__ toff,    // LQ x 4 x 2 x 2
    float* __restrict__ mid)           // LQ x 256
{
    __shared__ float4 smw[256];
    __shared__ int4   sma[256];

    const int q    = blockIdx.x;
    const int warp = threadIdx.x >> 5;   // head
    const int lane = threadIdx.x & 31;
    const int h = warp;
    const int l = lane >> 3;             // level
    const int p = lane & 7;              // point within level

    const int   Wl[4]  = {64, 32, 16, 8};
    const int   THl[4] = {192, 96, 48, 24};
    const int   STl[4] = {0, 12288, 15360, 16128};
    const int   Wv = Wl[l], TH = THl[l], start = STl[l];
    const float invW = 1.0f / (float)Wv, invTH = 1.0f / (float)TH;

    const float* prow = proj + (size_t)q * PROJN;

    int logit_col = (p < 4) ? (512 + h * 16 + l * 4 + p)
                            : (640 + h * 16 + l * 4 + (p - 4));
    float logit = prow[logit_col];
    float mx = logit;
    #pragma unroll
    for (int off = 16; off; off >>= 1) mx = fmaxf(mx, __shfl_xor_sync(0xffffffffu, mx, off));
    float e = __expf(logit - mx);
    float s = e;
    #pragma unroll
    for (int off = 16; off; off >>= 1) s += __shfl_xor_sync(0xffffffffu, s, off);
    float attnw = e / s;

    float rx = refp[q * 8 + l * 2 + 0];
    float ry = refp[q * 8 + l * 2 + 1];
    float ox, oy;
    if (p < 4) {
        int col = ((h * 4 + l) * 4 + p) * 2;                 // cso
        ox = prow[col + 0] * invW;
        oy = prow[col + 1] * invTH;
    } else {
        int tw = (p - 4) >> 1, tp = (p - 4) & 1;
        int col = 256 + (((h * 4 + l) * 2 + tw) * 2 + tp) * 2;  // tso
        int tob = ((q * 4 + l) * 2 + tw) * 2;
        ox = toff[tob + 0] + prow[col + 0] * invW;
        oy = toff[tob + 1] + prow[col + 1] * invTH;
    }
    float x = (rx + ox) * (float)Wv - 0.5f;
    float y = (ry + oy) * (float)TH - 0.5f;

    float x0f = floorf(x), y0f = floorf(y);
    float lx = x - x0f, ly = y - y0f;
    int x0 = (int)x0f, y0 = (int)y0f;
    int x1 = x0 + 1,   y1 = y0 + 1;

    bool ix0 = (x0 >= 0) & (x0 < Wv);
    bool ix1 = (x1 >= 0) & (x1 < Wv);
    bool iy0 = (y0 >= 0) & (y0 < TH);
    bool iy1 = (y1 >= 0) & (y1 < TH);
    int cx0 = min(max(x0, 0), Wv - 1);
    int cx1 = min(max(x1, 0), Wv - 1);
    int cy0 = min(max(y0, 0), TH - 1);
    int cy1 = min(max(y1, 0), TH - 1);

    float4 w;
    w.x = attnw * (1.f - lx) * (1.f - ly) * (float)(ix0 & iy0);
    w.y = attnw * lx         * (1.f - ly) * (float)(ix1 & iy0);
    w.z = attnw * (1.f - lx) * ly         * (float)(ix0 & iy1);
    w.w = attnw * lx         * ly         * (float)(ix1 & iy1);

    const int hbase = h * DHEAD;
    int4 a;
    a.x = (start + cy0 * Wv + cx0) * DIM + hbase;
    a.y = (start + cy0 * Wv + cx1) * DIM + hbase;
    a.z = (start + cy1 * Wv + cx0) * DIM + hbase;
    a.w = (start + cy1 * Wv + cx1) * DIM + hbase;

    smw[threadIdx.x] = w;
    sma[threadIdx.x] = a;
    __syncwarp();

    float acc = 0.f;
    const int sbase = warp << 5;
    #pragma unroll 4
    for (int i = 0; i < 32; ++i) {
        float4 wi = smw[sbase + i];
        int4   ai = sma[sbase + i];
        acc += wi.x * __ldg(value + ai.x + lane);
        acc += wi.y * __ldg(value + ai.y + lane);
        acc += wi.z * __ldg(value + ai.z + lane);
        acc += wi.w * __ldg(value + ai.w + lane);
    }
    mid[(size_t)q * DIM + hbase + lane] = acc;
}

// ---------------- launch ----------------
extern "C" void kernel_launch(void* const* d_in, const int* in_sizes, int n_in,
                              void* d_out, int out_size)
{
    const float* query = (const float*)d_in[0];
    const float* refp  = (const float*)d_in[1];
    const float* toff  = (const float*)d_in[2];
    const float* inpf  = (const float*)d_in[3];
    const float* W_so  = (const float*)d_in[6];
    const float* b_so  = (const float*)d_in[7];
    const float* W_tso = (const float*)d_in[8];
    const float* b_tso = (const float*)d_in[9];
    const float* W_aw  = (const float*)d_in[10];
    const float* b_aw  = (const float*)d_in[11];
    const float* W_taw = (const float*)d_in[12];
    const float* b_taw = (const float*)d_in[13];
    const float* W_v   = (const float*)d_in[14];
    const float* b_v   = (const float*)d_in[15];
    const float* W_o   = (const float*)d_in[16];
    const float* b_o   = (const float*)d_in[17];
    float* out = (float*)d_out;

    float *value, *proj, *mid;
    cudaGetSymbolAddress((void**)&value, g_value);
    cudaGetSymbolAddress((void**)&proj,  g_proj);
    cudaGetSymbolAddress((void**)&mid,   g_mid);

    dim3 blk(128);
    const int MB = LQ / BM;  // 255
    // value = input_flatten @ W_v + b_v
    sgemm_bias_v2<<<dim3(256 / BN, MB), blk>>>(inpf, W_v, b_v, value, 256, DIM);
    // fused projection buffer: [cso | tso | caw | taw]
    sgemm_bias_v2<<<dim3(256 / BN, MB), blk>>>(query, W_so,  b_so,  proj + 0,   256, PROJN);
    sgemm_bias_v2<<<dim3(256 / BN, MB), blk>>>(query, W_tso, b_tso, proj + 256, 256, PROJN);
    sgemm_bias_v2<<<dim3(128 / BN, MB), blk>>>(query, W_aw,  b_aw,  proj + 512, 128, PROJN);
    sgemm_bias_v2<<<dim3(128 / BN, MB), blk>>>(query, W_taw, b_taw, proj + 640, 128, PROJN);
    // softmax + deformable bilinear sampling
    deform_kernel<<<LQ, 256>>>(proj, value, refp, toff, mid);
    // out = mid @ W_o + b_o
    sgemm_bias_v2<<<dim3(256 / BN, MB), blk>>>(mid, W_o, b_o, out, 256, DIM);
}